// round 4
// baseline (speedup 1.0000x reference)
#include <cuda_runtime.h>

typedef unsigned long long ull;
typedef unsigned int uint_;

#define B_   8
#define C_   256
#define H_   128
#define W_   128
#define CR_  32
#define HW_  (H_ * W_)

// ---------------- scratch (device globals; no runtime allocation) -------------
__device__ float g_q  [B_ * CR_ * HW_];   // (b, cr, h, w)
__device__ float g_k  [B_ * CR_ * HW_];
__device__ float g_v  [B_ * CR_ * HW_];
__device__ float g_qt [B_ * CR_ * HW_];   // (b, cr, w, h)
__device__ float g_kt [B_ * CR_ * HW_];
__device__ float g_vt [B_ * CR_ * HW_];
__device__ float g_oH [B_ * CR_ * HW_];   // (b, cr, w, h)
__device__ float g_oHt[B_ * CR_ * HW_];   // (b, cr, h, w)
__device__ float g_oW [B_ * CR_ * HW_];   // (b, cr, h, w)
__device__ float g_mH [B_ * HW_];
__device__ float g_sH [B_ * HW_];
__device__ float g_mW [B_ * HW_];
__device__ float g_sW [B_ * HW_];

// ---------------- packed f32x2 helpers ---------------------------------------
__device__ __forceinline__ ull fma2(ull a, ull b, ull c) {
    ull d;
    asm("fma.rn.f32x2 %0, %1, %2, %3;" : "=l"(d) : "l"(a), "l"(b), "l"(c));
    return d;
}
__device__ __forceinline__ ull splat2(float f) {
    ull r; uint_ u = __float_as_uint(f);
    asm("mov.b64 %0, {%1, %1};" : "=l"(r) : "r"(u));
    return r;
}
__device__ __forceinline__ ull pack2(float lo, float hi) {
    ull r;
    asm("mov.b64 %0, {%1, %2};" : "=l"(r)
        : "r"(__float_as_uint(lo)), "r"(__float_as_uint(hi)));
    return r;
}
__device__ __forceinline__ float2 unpack2(ull u) {
    uint_ lo, hi;
    asm("mov.b64 {%0, %1}, %2;" : "=r"(lo), "=r"(hi) : "l"(u));
    return make_float2(__uint_as_float(lo), __uint_as_float(hi));
}
__device__ __forceinline__ ull ldpair(const float* p) {
    union { float2 f2; ull u; } t;
    t.f2 = *reinterpret_cast<const float2*>(p);
    return t.u;
}

union F4U { float4 f4; ull u[2]; };

// ---------------- kernel 1: fused q/k/v projection (round-1 version) ---------
__global__ void __launch_bounds__(256) proj_kernel(
    const float* __restrict__ x,
    const float* __restrict__ Wq, const float* __restrict__ bq,
    const float* __restrict__ Wk, const float* __restrict__ bk,
    const float* __restrict__ Wv, const float* __restrict__ bv)
{
    __shared__ float xs[32 * 128];
    __shared__ float ws[96 * 32];

    int h = blockIdx.x, b = blockIdx.y;
    int tid = threadIdx.x;
    int ty = tid >> 5, tx = tid & 31;

    const float* xb = x + (size_t)b * C_ * HW_ + (size_t)h * W_;

    ull acc[12][2];
#pragma unroll
    for (int j = 0; j < 12; j++) { acc[j][0] = 0ull; acc[j][1] = 0ull; }

    for (int kc = 0; kc < 8; kc++) {
#pragma unroll
        for (int idx = tid; idx < 32 * 128; idx += 256) {
            int cc = idx >> 7, w = idx & 127;
            xs[idx] = xb[(size_t)(kc * 32 + cc) * HW_ + w];
        }
#pragma unroll
        for (int idx = tid; idx < 96 * 32; idx += 256) {
            int r = idx >> 5, cc = idx & 31;
            float wv;
            if (r < 32)      wv = Wq[r * C_ + kc * 32 + cc];
            else if (r < 64) wv = Wk[(r - 32) * C_ + kc * 32 + cc];
            else             wv = Wv[(r - 64) * C_ + kc * 32 + cc];
            ws[idx] = wv;
        }
        __syncthreads();

#pragma unroll 4
        for (int c = 0; c < 32; c++) {
            ull x0 = ldpair(&xs[c * 128 + 2 * tx]);
            ull x1 = ldpair(&xs[c * 128 + 2 * tx + 64]);
#pragma unroll
            for (int j = 0; j < 12; j++) {
                ull wv = splat2(ws[(ty + 8 * j) * 32 + c]);
                acc[j][0] = fma2(wv, x0, acc[j][0]);
                acc[j][1] = fma2(wv, x1, acc[j][1]);
            }
        }
        __syncthreads();
    }

#pragma unroll
    for (int j = 0; j < 12; j++) {
        int r = ty + 8 * j;
        float bias; float* dst;
        if (r < 32)      { bias = bq[r];      dst = g_q + ((size_t)(b * CR_ + r)      * H_ + h) * W_; }
        else if (r < 64) { bias = bk[r - 32]; dst = g_k + ((size_t)(b * CR_ + r - 32) * H_ + h) * W_; }
        else             { bias = bv[r - 64]; dst = g_v + ((size_t)(b * CR_ + r - 64) * H_ + h) * W_; }
#pragma unroll
        for (int u = 0; u < 2; u++) {
            float2 v = unpack2(acc[j][u]);
            v.x += bias; v.y += bias;
            *reinterpret_cast<float2*>(&dst[2 * tx + 64 * u]) = v;
        }
    }
}

// ---------------- kernel 2: HxW tile transpose --------------------------------
__global__ void __launch_bounds__(256) transpose_kernel(int base_arr)
{
    __shared__ float tile[32][33];
    int zc = blockIdx.z;
    int arr = base_arr + (zc >> 8), m = zc & 255;
    const float* src; float* dst;
    if      (arr == 0) { src = g_q;  dst = g_qt;  }
    else if (arr == 1) { src = g_k;  dst = g_kt;  }
    else if (arr == 2) { src = g_v;  dst = g_vt;  }
    else               { src = g_oH; dst = g_oHt; }
    src += (size_t)m * HW_;
    dst += (size_t)m * HW_;
    int x0 = blockIdx.x * 32, y0 = blockIdx.y * 32;
    int tx = threadIdx.x, ty = threadIdx.y;
#pragma unroll
    for (int r = 0; r < 32; r += 8)
        tile[ty + r][tx] = src[(size_t)(y0 + ty + r) * W_ + x0 + tx];
    __syncthreads();
#pragma unroll
    for (int r = 0; r < 32; r += 8)
        dst[(size_t)(x0 + ty + r) * H_ + y0 + tx] = tile[tx][ty + r];
}

// ---------------- kernel 3: attention path v3 ---------------------------------
// grid (128, B), 256 threads. Transposed-energy layout + LDS.128 broadcasts.
// Warp w owns energy columns i = 16w..16w+15; lane l owns rows r = {2l,2l+1,2l+64,2l+65}.
#define ATTN_SMEM ((32*132 + 32*132 + 128*33 + 128*132 + 1024 + 1024) * 4)

__global__ void __launch_bounds__(256) attn_kernel(int transposed)
{
    extern __shared__ float sm[];
    float* Qs   = sm;                  // 32 x 132  (also reused as 32x130 output stage)
    float* Ks   = Qs + 32 * 132;       // 32 x 132
    float* Vst  = Ks + 32 * 132;       // 128 x 33   ([i][c])
    float* Et   = Vst + 128 * 33;      // 128 x 132  (probs, [i][r])
    float* Red1 = Et + 128 * 132;      // 8 x 128
    float* Red2 = Red1 + 1024;         // 8 x 128

    const float* qin = transposed ? g_qt : g_q;
    const float* kin = transposed ? g_kt : g_k;
    const float* vin = transposed ? g_vt : g_v;
    float* outp  = transposed ? g_oH : g_oW;
    float* mstat = transposed ? g_mH : g_mW;
    float* sstat = transposed ? g_sH : g_sW;

    int X = blockIdx.x, b = blockIdx.y;
    size_t base = (size_t)b * CR_ * HW_ + (size_t)X * W_;
    int tid = threadIdx.x, w = tid >> 5, l = tid & 31;

    for (int idx = tid; idx < CR_ * 128; idx += 256) {
        int c = idx >> 7, e = idx & 127;
        float qv = qin[base + (size_t)c * HW_ + e];
        float kv = kin[base + (size_t)c * HW_ + e];
        float vv = vin[base + (size_t)c * HW_ + e];
        Qs[c * 132 + e] = qv;
        Ks[c * 132 + e] = kv;
        Vst[e * 33 + c] = vv;
    }
    __syncthreads();

    // ---- gram (transposed): Gt[i][r] = sum_c K[c][i] * Q[c][r] ----
    ull acc0[16], acc1[16];
#pragma unroll
    for (int t = 0; t < 16; t++) { acc0[t] = 0ull; acc1[t] = 0ull; }

#pragma unroll 2
    for (int c = 0; c < 32; c++) {
        ull q0 = ldpair(&Qs[c * 132 + 2 * l]);
        ull q1 = ldpair(&Qs[c * 132 + 2 * l + 64]);
        float4 k0 = *reinterpret_cast<const float4*>(&Ks[c * 132 + 16 * w]);
        float4 k1 = *reinterpret_cast<const float4*>(&Ks[c * 132 + 16 * w + 4]);
        float4 k2 = *reinterpret_cast<const float4*>(&Ks[c * 132 + 16 * w + 8]);
        float4 k3 = *reinterpret_cast<const float4*>(&Ks[c * 132 + 16 * w + 12]);
#define GSTEP(T, KF) { ull kv = splat2(KF); \
        acc0[T] = fma2(kv, q0, acc0[T]); acc1[T] = fma2(kv, q1, acc1[T]); }
        GSTEP(0,  k0.x) GSTEP(1,  k0.y) GSTEP(2,  k0.z) GSTEP(3,  k0.w)
        GSTEP(4,  k1.x) GSTEP(5,  k1.y) GSTEP(6,  k1.z) GSTEP(7,  k1.w)
        GSTEP(8,  k2.x) GSTEP(9,  k2.y) GSTEP(10, k2.z) GSTEP(11, k2.w)
        GSTEP(12, k3.x) GSTEP(13, k3.y) GSTEP(14, k3.z) GSTEP(15, k3.w)
#undef GSTEP
    }

    // ---- mask + local max over this warp's 16 i's (per r) ----
    float m0x = -1e30f, m0y = -1e30f, m1x = -1e30f, m1y = -1e30f;
#pragma unroll
    for (int t = 0; t < 16; t++) {
        float2 u0 = unpack2(acc0[t]);
        float2 u1 = unpack2(acc1[t]);
        if (transposed) {
            int i = 16 * w + t;
            if (i == 2 * l)      u0.x = -1e30f;
            if (i == 2 * l + 1)  u0.y = -1e30f;
            if (i == 2 * l + 64) u1.x = -1e30f;
            if (i == 2 * l + 65) u1.y = -1e30f;
            acc0[t] = pack2(u0.x, u0.y);
            acc1[t] = pack2(u1.x, u1.y);
        }
        m0x = fmaxf(m0x, u0.x); m0y = fmaxf(m0y, u0.y);
        m1x = fmaxf(m1x, u1.x); m1y = fmaxf(m1y, u1.y);
    }
    *reinterpret_cast<float2*>(&Red1[w * 128 + 2 * l])      = make_float2(m0x, m0y);
    *reinterpret_cast<float2*>(&Red1[w * 128 + 2 * l + 64]) = make_float2(m1x, m1y);
    __syncthreads();

    // ---- global max per r ----
    float M0x = -1e30f, M0y = -1e30f, M1x = -1e30f, M1y = -1e30f;
#pragma unroll
    for (int w2 = 0; w2 < 8; w2++) {
        float2 f0 = *reinterpret_cast<const float2*>(&Red1[w2 * 128 + 2 * l]);
        float2 f1 = *reinterpret_cast<const float2*>(&Red1[w2 * 128 + 2 * l + 64]);
        M0x = fmaxf(M0x, f0.x); M0y = fmaxf(M0y, f0.y);
        M1x = fmaxf(M1x, f1.x); M1y = fmaxf(M1y, f1.y);
    }

    // ---- exp, write transposed probs, local sums ----
    float s0x = 0.f, s0y = 0.f, s1x = 0.f, s1y = 0.f;
#pragma unroll
    for (int t = 0; t < 16; t++) {
        float2 u0 = unpack2(acc0[t]);
        float2 u1 = unpack2(acc1[t]);
        float p0 = __expf(u0.x - M0x), p1 = __expf(u0.y - M0y);
        float p2 = __expf(u1.x - M1x), p3 = __expf(u1.y - M1y);
        s0x += p0; s0y += p1; s1x += p2; s1y += p3;
        int i = 16 * w + t;
        *reinterpret_cast<float2*>(&Et[i * 132 + 2 * l])      = make_float2(p0, p1);
        *reinterpret_cast<float2*>(&Et[i * 132 + 2 * l + 64]) = make_float2(p2, p3);
    }
    *reinterpret_cast<float2*>(&Red2[w * 128 + 2 * l])      = make_float2(s0x, s0y);
    *reinterpret_cast<float2*>(&Red2[w * 128 + 2 * l + 64]) = make_float2(s1x, s1y);
    __syncthreads();

    // ---- global sum per r + stats (warp 0 writes) ----
    if (w == 0) {
        float S0x = 0.f, S0y = 0.f, S1x = 0.f, S1y = 0.f;
#pragma unroll
        for (int w2 = 0; w2 < 8; w2++) {
            float2 f0 = *reinterpret_cast<const float2*>(&Red2[w2 * 128 + 2 * l]);
            float2 f1 = *reinterpret_cast<const float2*>(&Red2[w2 * 128 + 2 * l + 64]);
            S0x += f0.x; S0y += f0.y; S1x += f1.x; S1y += f1.y;
        }
        int r0 = 2 * l, r1 = 2 * l + 1, r2 = 2 * l + 64, r3 = 2 * l + 65;
#define STATW(R, MV, SV) { \
        size_t sidx = transposed ? ((size_t)(b * H_ + (R)) * W_ + X) \
                                 : ((size_t)(b * H_ + X) * W_ + (R)); \
        mstat[sidx] = MV; sstat[sidx] = SV; }
        STATW(r0, M0x, S0x) STATW(r1, M0y, S0y) STATW(r2, M1x, S1x) STATW(r3, M1y, S1y)
#undef STATW
    }

    // ---- aggregation: out[c=l][r] = sum_i V[i][c] * P[i][r] ----
    // warp w covers rows r = 16w..16w+15, accumulated as 8 r-pairs.
    ull g[8];
#pragma unroll
    for (int tp = 0; tp < 8; tp++) g[tp] = 0ull;

#pragma unroll 2
    for (int i = 0; i < 128; i++) {
        ull vvs = splat2(Vst[i * 33 + l]);
        F4U e0, e1, e2, e3;
        e0.f4 = *reinterpret_cast<const float4*>(&Et[i * 132 + 16 * w]);
        e1.f4 = *reinterpret_cast<const float4*>(&Et[i * 132 + 16 * w + 4]);
        e2.f4 = *reinterpret_cast<const float4*>(&Et[i * 132 + 16 * w + 8]);
        e3.f4 = *reinterpret_cast<const float4*>(&Et[i * 132 + 16 * w + 12]);
        g[0] = fma2(vvs, e0.u[0], g[0]); g[1] = fma2(vvs, e0.u[1], g[1]);
        g[2] = fma2(vvs, e1.u[0], g[2]); g[3] = fma2(vvs, e1.u[1], g[3]);
        g[4] = fma2(vvs, e2.u[0], g[4]); g[5] = fma2(vvs, e2.u[1], g[5]);
        g[6] = fma2(vvs, e3.u[0], g[6]); g[7] = fma2(vvs, e3.u[1], g[7]);
    }

    // ---- stage (reuse Qs, stride 130) + coalesced global write ----
    float* stg = Qs;
#pragma unroll
    for (int tp = 0; tp < 8; tp++) {
        float2 v = unpack2(g[tp]);
        *reinterpret_cast<float2*>(&stg[l * 130 + 16 * w + 2 * tp]) = v;
    }
    __syncthreads();
    for (int idx = tid; idx < CR_ * 128; idx += 256) {
        int c = idx >> 7, e = idx & 127;
        outp[base + (size_t)c * HW_ + e] = stg[c * 130 + e];
    }
}

// ---------------- kernel 4: softmax merge + Wz conv + bias + residual --------
#define COMB_SMEM ((32 * 130 + 256 * 32 + 256) * 4)

__global__ void __launch_bounds__(512) combine_kernel(
    const float* __restrict__ x, const float* __restrict__ Wz,
    const float* __restrict__ bz, float* __restrict__ out)
{
    extern __shared__ float sm[];
    float* mg  = sm;                        // 32 x 130
    float* Wzs = sm + 32 * 130;             // 256 x 32
    float* fH  = sm + 32 * 130 + 256 * 32;  // 128
    float* fW  = fH + 128;                  // 128

    int h = blockIdx.x, b = blockIdx.y;
    int tid = threadIdx.x, wp = tid >> 5, lane = tid & 31;

    if (tid < 128) {
        int w = tid;
        size_t sidx = (size_t)(b * H_ + h) * W_ + w;
        float mh = g_mH[sidx], mw = g_mW[sidx];
        float sh = g_sH[sidx], sw = g_sW[sidx];
        float m  = fmaxf(mh, mw);
        float eh = __expf(mh - m), ew = __expf(mw - m);
        float inv = 1.0f / (sh * eh + sw * ew);
        fH[w] = eh * inv;
        fW[w] = ew * inv;
    }
    for (int idx = tid; idx < 256 * 32; idx += 512)
        Wzs[idx] = Wz[idx];
    __syncthreads();

    for (int idx = tid; idx < 32 * 128; idx += 512) {
        int c = idx >> 7, w = idx & 127;
        size_t off = (size_t)(b * CR_ + c) * HW_ + (size_t)h * W_ + w;
        mg[c * 130 + w] = g_oHt[off] * fH[w] + g_oW[off] * fW[w];
    }
    __syncthreads();

    ull acc[16][2];
#pragma unroll
    for (int j = 0; j < 16; j++) { acc[j][0] = 0ull; acc[j][1] = 0ull; }

#pragma unroll 4
    for (int c = 0; c < 32; c++) {
        ull m0 = ldpair(&mg[c * 130 + 2 * lane]);
        ull m1 = ldpair(&mg[c * 130 + 2 * lane + 64]);
#pragma unroll
        for (int j = 0; j < 16; j++) {
            ull wv = splat2(Wzs[(wp + 16 * j) * 32 + c]);
            acc[j][0] = fma2(wv, m0, acc[j][0]);
            acc[j][1] = fma2(wv, m1, acc[j][1]);
        }
    }

#pragma unroll
    for (int j = 0; j < 16; j++) {
        int o = wp + 16 * j;
        float bias = bz[o];
        size_t obase = ((size_t)(b * C_ + o) * H_ + h) * W_;
#pragma unroll
        for (int u = 0; u < 2; u++) {
            int w = 2 * lane + 64 * u;
            float2 xv = *reinterpret_cast<const float2*>(&x[obase + w]);
            float2 a  = unpack2(acc[j][u]);
            a.x += bias + xv.x;
            a.y += bias + xv.y;
            *reinterpret_cast<float2*>(&out[obase + w]) = a;
        }
    }
}

// ---------------- launch ------------------------------------------------------
extern "C" void kernel_launch(void* const* d_in, const int* in_sizes, int n_in,
                              void* d_out, int out_size)
{
    const float* x  = (const float*)d_in[0];
    const float* Wq = (const float*)d_in[1];
    const float* bq = (const float*)d_in[2];
    const float* Wk = (const float*)d_in[3];
    const float* bk = (const float*)d_in[4];
    const float* Wv = (const float*)d_in[5];
    const float* bv = (const float*)d_in[6];
    const float* Wz = (const float*)d_in[7];
    const float* bz = (const float*)d_in[8];
    float* out = (float*)d_out;

    cudaFuncSetAttribute(attn_kernel,    cudaFuncAttributeMaxDynamicSharedMemorySize, ATTN_SMEM);
    cudaFuncSetAttribute(combine_kernel, cudaFuncAttributeMaxDynamicSharedMemorySize, COMB_SMEM);

    proj_kernel<<<dim3(H_, B_), 256>>>(x, Wq, bq, Wk, bk, Wv, bv);
    transpose_kernel<<<dim3(4, 4, 3 * 256), dim3(32, 8)>>>(0);   // q,k,v -> qt,kt,vt
    attn_kernel<<<dim3(W_, B_), 256, ATTN_SMEM>>>(1);            // H path
    attn_kernel<<<dim3(H_, B_), 256, ATTN_SMEM>>>(0);            // W path
    transpose_kernel<<<dim3(4, 4, 256), dim3(32, 8)>>>(3);       // oH -> oHt
    combine_kernel<<<dim3(H_, B_), 512, COMB_SMEM>>>(x, Wz, bz, out);
}

// round 5
// speedup vs baseline: 1.1198x; 1.1198x over previous
#include <cuda_runtime.h>

typedef unsigned long long ull;
typedef unsigned int uint_;

#define B_   8
#define C_   256
#define H_   128
#define W_   128
#define CR_  32
#define HW_  (H_ * W_)

// ---------------- scratch (device globals; no runtime allocation) -------------
__device__ float g_q  [B_ * CR_ * HW_];   // (b, cr, h, w)
__device__ float g_k  [B_ * CR_ * HW_];
__device__ float g_v  [B_ * CR_ * HW_];
__device__ float g_qt [B_ * CR_ * HW_];   // (b, cr, w, h)
__device__ float g_kt [B_ * CR_ * HW_];
__device__ float g_vt [B_ * CR_ * HW_];
__device__ float g_oH [B_ * CR_ * HW_];   // (b, cr, w, h)
__device__ float g_oHt[B_ * CR_ * HW_];   // (b, cr, h, w)
__device__ float g_oW [B_ * CR_ * HW_];   // (b, cr, h, w)
__device__ float g_mH [B_ * HW_];
__device__ float g_sH [B_ * HW_];
__device__ float g_mW [B_ * HW_];
__device__ float g_sW [B_ * HW_];

// ---------------- packed f32x2 helpers ---------------------------------------
__device__ __forceinline__ ull fma2(ull a, ull b, ull c) {
    ull d;
    asm("fma.rn.f32x2 %0, %1, %2, %3;" : "=l"(d) : "l"(a), "l"(b), "l"(c));
    return d;
}
__device__ __forceinline__ ull splat2(float f) {
    ull r; uint_ u = __float_as_uint(f);
    asm("mov.b64 %0, {%1, %1};" : "=l"(r) : "r"(u));
    return r;
}
__device__ __forceinline__ ull pack2(float lo, float hi) {
    ull r;
    asm("mov.b64 %0, {%1, %2};" : "=l"(r)
        : "r"(__float_as_uint(lo)), "r"(__float_as_uint(hi)));
    return r;
}
__device__ __forceinline__ float2 unpack2(ull u) {
    uint_ lo, hi;
    asm("mov.b64 {%0, %1}, %2;" : "=r"(lo), "=r"(hi) : "l"(u));
    return make_float2(__uint_as_float(lo), __uint_as_float(hi));
}
__device__ __forceinline__ ull ldpair(const float* p) {
    union { float2 f2; ull u; } t;
    t.f2 = *reinterpret_cast<const float2*>(p);
    return t.u;
}

union F4U { float4 f4; ull u[2]; };

// ---------------- kernel 1: fused q/k/v projection (round-1 version) ---------
__global__ void __launch_bounds__(256) proj_kernel(
    const float* __restrict__ x,
    const float* __restrict__ Wq, const float* __restrict__ bq,
    const float* __restrict__ Wk, const float* __restrict__ bk,
    const float* __restrict__ Wv, const float* __restrict__ bv)
{
    __shared__ float xs[32 * 128];
    __shared__ float ws[96 * 32];

    int h = blockIdx.x, b = blockIdx.y;
    int tid = threadIdx.x;
    int ty = tid >> 5, tx = tid & 31;

    const float* xb = x + (size_t)b * C_ * HW_ + (size_t)h * W_;

    ull acc[12][2];
#pragma unroll
    for (int j = 0; j < 12; j++) { acc[j][0] = 0ull; acc[j][1] = 0ull; }

    for (int kc = 0; kc < 8; kc++) {
#pragma unroll
        for (int idx = tid; idx < 32 * 128; idx += 256) {
            int cc = idx >> 7, w = idx & 127;
            xs[idx] = xb[(size_t)(kc * 32 + cc) * HW_ + w];
        }
#pragma unroll
        for (int idx = tid; idx < 96 * 32; idx += 256) {
            int r = idx >> 5, cc = idx & 31;
            float wv;
            if (r < 32)      wv = Wq[r * C_ + kc * 32 + cc];
            else if (r < 64) wv = Wk[(r - 32) * C_ + kc * 32 + cc];
            else             wv = Wv[(r - 64) * C_ + kc * 32 + cc];
            ws[idx] = wv;
        }
        __syncthreads();

#pragma unroll 4
        for (int c = 0; c < 32; c++) {
            ull x0 = ldpair(&xs[c * 128 + 2 * tx]);
            ull x1 = ldpair(&xs[c * 128 + 2 * tx + 64]);
#pragma unroll
            for (int j = 0; j < 12; j++) {
                ull wv = splat2(ws[(ty + 8 * j) * 32 + c]);
                acc[j][0] = fma2(wv, x0, acc[j][0]);
                acc[j][1] = fma2(wv, x1, acc[j][1]);
            }
        }
        __syncthreads();
    }

#pragma unroll
    for (int j = 0; j < 12; j++) {
        int r = ty + 8 * j;
        float bias; float* dst;
        if (r < 32)      { bias = bq[r];      dst = g_q + ((size_t)(b * CR_ + r)      * H_ + h) * W_; }
        else if (r < 64) { bias = bk[r - 32]; dst = g_k + ((size_t)(b * CR_ + r - 32) * H_ + h) * W_; }
        else             { bias = bv[r - 64]; dst = g_v + ((size_t)(b * CR_ + r - 64) * H_ + h) * W_; }
#pragma unroll
        for (int u = 0; u < 2; u++) {
            float2 v = unpack2(acc[j][u]);
            v.x += bias; v.y += bias;
            *reinterpret_cast<float2*>(&dst[2 * tx + 64 * u]) = v;
        }
    }
}

// ---------------- kernel 2: HxW tile transpose --------------------------------
__global__ void __launch_bounds__(256) transpose_kernel(int base_arr)
{
    __shared__ float tile[32][33];
    int zc = blockIdx.z;
    int arr = base_arr + (zc >> 8), m = zc & 255;
    const float* src; float* dst;
    if      (arr == 0) { src = g_q;  dst = g_qt;  }
    else if (arr == 1) { src = g_k;  dst = g_kt;  }
    else if (arr == 2) { src = g_v;  dst = g_vt;  }
    else               { src = g_oH; dst = g_oHt; }
    src += (size_t)m * HW_;
    dst += (size_t)m * HW_;
    int x0 = blockIdx.x * 32, y0 = blockIdx.y * 32;
    int tx = threadIdx.x, ty = threadIdx.y;
#pragma unroll
    for (int r = 0; r < 32; r += 8)
        tile[ty + r][tx] = src[(size_t)(y0 + ty + r) * W_ + x0 + tx];
    __syncthreads();
#pragma unroll
    for (int r = 0; r < 32; r += 8)
        dst[(size_t)(x0 + ty + r) * H_ + y0 + tx] = tile[tx][ty + r];
}

// ---------------- kernel 3: attention path (round-1 layout + LDS.128) --------
// grid (128, B), 256 threads. Warp owns 16 rows; lane owns i = {2l,2l+1,2l+64,2l+65}.
// Smem = 115712 B (same as round-1) -> 2 CTAs/SM.
#define ATTN_SMEM ((32 * 132 + 32 * 128 + 128 * 33 + 128 * 128) * 4)

__global__ void __launch_bounds__(256) attn_kernel(int transposed)
{
    extern __shared__ float sm[];
    float* Qs  = sm;                        // 32 x 132 (16B-aligned row groups)
    float* Ks  = sm + 32 * 132;             // 32 x 128
    float* Vst = Ks + 32 * 128;             // 128 x 33  ([i][c])
    float* E   = Vst + 128 * 33;            // 128 x 128

    const float* qin = transposed ? g_qt : g_q;
    const float* kin = transposed ? g_kt : g_k;
    const float* vin = transposed ? g_vt : g_v;
    float* outp  = transposed ? g_oH : g_oW;
    float* mstat = transposed ? g_mH : g_mW;
    float* sstat = transposed ? g_sH : g_sW;

    int X = blockIdx.x, b = blockIdx.y;
    size_t base = (size_t)b * CR_ * HW_ + (size_t)X * W_;
    int tid = threadIdx.x, warp = tid >> 5, lane = tid & 31;

    for (int idx = tid; idx < CR_ * 128; idx += 256) {
        int c = idx >> 7, e = idx & 127;
        Qs[c * 132 + e] = qin[base + (size_t)c * HW_ + e];
        Ks[c * 128 + e] = kin[base + (size_t)c * HW_ + e];
        Vst[e * 33 + c] = vin[base + (size_t)c * HW_ + e];
    }
    __syncthreads();

    // ---- gram: E[r][i] = sum_c Q[c][r] * K[c][i]; Q broadcasts via LDS.128 ----
    ull acc[16][2];
#pragma unroll
    for (int t = 0; t < 16; t++) { acc[t][0] = 0ull; acc[t][1] = 0ull; }

#pragma unroll 2
    for (int c = 0; c < 32; c++) {
        ull k0 = ldpair(&Ks[c * 128 + 2 * lane]);
        ull k1 = ldpair(&Ks[c * 128 + 2 * lane + 64]);
        float4 q0 = *reinterpret_cast<const float4*>(&Qs[c * 132 + 16 * warp]);
        float4 q1 = *reinterpret_cast<const float4*>(&Qs[c * 132 + 16 * warp + 4]);
        float4 q2 = *reinterpret_cast<const float4*>(&Qs[c * 132 + 16 * warp + 8]);
        float4 q3 = *reinterpret_cast<const float4*>(&Qs[c * 132 + 16 * warp + 12]);
#define GSTEP(T, QF) { ull qv = splat2(QF); \
        acc[T][0] = fma2(qv, k0, acc[T][0]); acc[T][1] = fma2(qv, k1, acc[T][1]); }
        GSTEP(0,  q0.x) GSTEP(1,  q0.y) GSTEP(2,  q0.z) GSTEP(3,  q0.w)
        GSTEP(4,  q1.x) GSTEP(5,  q1.y) GSTEP(6,  q1.z) GSTEP(7,  q1.w)
        GSTEP(8,  q2.x) GSTEP(9,  q2.y) GSTEP(10, q2.z) GSTEP(11, q2.w)
        GSTEP(12, q3.x) GSTEP(13, q3.y) GSTEP(14, q3.z) GSTEP(15, q3.w)
#undef GSTEP
    }

    // ---- per-row softmax (unchanged from round-1) ----
#pragma unroll
    for (int t = 0; t < 16; t++) {
        int r = warp * 16 + t;
        float2 a0 = unpack2(acc[t][0]);
        float2 a1 = unpack2(acc[t][1]);
        if (transposed) {
            int i0 = 2 * lane;
            if (i0      == r) a0.x = -1e30f;
            if (i0 + 1  == r) a0.y = -1e30f;
            if (i0 + 64 == r) a1.x = -1e30f;
            if (i0 + 65 == r) a1.y = -1e30f;
        }
        float mx = fmaxf(fmaxf(a0.x, a0.y), fmaxf(a1.x, a1.y));
#pragma unroll
        for (int o = 16; o > 0; o >>= 1) mx = fmaxf(mx, __shfl_xor_sync(0xffffffffu, mx, o));
        float p0 = __expf(a0.x - mx), p1 = __expf(a0.y - mx);
        float p2 = __expf(a1.x - mx), p3 = __expf(a1.y - mx);
        float sum = (p0 + p1) + (p2 + p3);
#pragma unroll
        for (int o = 16; o > 0; o >>= 1) sum += __shfl_xor_sync(0xffffffffu, sum, o);
        *reinterpret_cast<float2*>(&E[r * 128 + 2 * lane])      = make_float2(p0, p1);
        *reinterpret_cast<float2*>(&E[r * 128 + 2 * lane + 64]) = make_float2(p2, p3);
        if (lane == 0) {
            size_t sidx = transposed ? ((size_t)(b * H_ + r) * W_ + X)
                                     : ((size_t)(b * H_ + X) * W_ + r);
            mstat[sidx] = mx;
            sstat[sidx] = sum;
        }
    }
    __syncthreads();

    // ---- aggregation: out[c=lane][r] = sum_i V[i][c] * P[r][i] ----
    // i in chunks of 8: V pairs in regs, P rows via 2x LDS.128 broadcast.
    ull agg[16];
#pragma unroll
    for (int t = 0; t < 16; t++) agg[t] = 0ull;

    for (int i = 0; i < 128; i += 8) {
        ull vv[4];
#pragma unroll
        for (int u = 0; u < 4; u++)
            vv[u] = pack2(Vst[(i + 2 * u) * 33 + lane], Vst[(i + 2 * u + 1) * 33 + lane]);
#pragma unroll
        for (int t = 0; t < 16; t++) {
            F4U e0, e1;
            e0.f4 = *reinterpret_cast<const float4*>(&E[(warp * 16 + t) * 128 + i]);
            e1.f4 = *reinterpret_cast<const float4*>(&E[(warp * 16 + t) * 128 + i + 4]);
            agg[t] = fma2(e0.u[0], vv[0], agg[t]);
            agg[t] = fma2(e0.u[1], vv[1], agg[t]);
            agg[t] = fma2(e1.u[0], vv[2], agg[t]);
            agg[t] = fma2(e1.u[1], vv[3], agg[t]);
        }
    }

    // ---- stage transposed into smem (reuse Qs, stride 130) + coalesced write ----
#pragma unroll
    for (int t = 0; t < 16; t++) {
        float2 s = unpack2(agg[t]);
        Qs[lane * 130 + warp * 16 + t] = s.x + s.y;
    }
    __syncthreads();
    for (int idx = tid; idx < CR_ * 128; idx += 256) {
        int c = idx >> 7, e = idx & 127;
        outp[base + (size_t)c * HW_ + e] = Qs[c * 130 + e];
    }
}

// ---------------- kernel 4: softmax merge + Wz conv + bias + residual --------
#define COMB_SMEM ((32 * 130 + 256 * 32 + 256) * 4)

__global__ void __launch_bounds__(512) combine_kernel(
    const float* __restrict__ x, const float* __restrict__ Wz,
    const float* __restrict__ bz, float* __restrict__ out)
{
    extern __shared__ float sm[];
    float* mg  = sm;                        // 32 x 130
    float* Wzs = sm + 32 * 130;             // 256 x 32
    float* fH  = sm + 32 * 130 + 256 * 32;  // 128
    float* fW  = fH + 128;                  // 128

    int h = blockIdx.x, b = blockIdx.y;
    int tid = threadIdx.x, wp = tid >> 5, lane = tid & 31;

    if (tid < 128) {
        int w = tid;
        size_t sidx = (size_t)(b * H_ + h) * W_ + w;
        float mh = g_mH[sidx], mw = g_mW[sidx];
        float sh = g_sH[sidx], sw = g_sW[sidx];
        float m  = fmaxf(mh, mw);
        float eh = __expf(mh - m), ew = __expf(mw - m);
        float inv = 1.0f / (sh * eh + sw * ew);
        fH[w] = eh * inv;
        fW[w] = ew * inv;
    }
    for (int idx = tid; idx < 256 * 32; idx += 512)
        Wzs[idx] = Wz[idx];
    __syncthreads();

    for (int idx = tid; idx < 32 * 128; idx += 512) {
        int c = idx >> 7, w = idx & 127;
        size_t off = (size_t)(b * CR_ + c) * HW_ + (size_t)h * W_ + w;
        mg[c * 130 + w] = g_oHt[off] * fH[w] + g_oW[off] * fW[w];
    }
    __syncthreads();

    ull acc[16][2];
#pragma unroll
    for (int j = 0; j < 16; j++) { acc[j][0] = 0ull; acc[j][1] = 0ull; }

#pragma unroll 4
    for (int c = 0; c < 32; c++) {
        ull m0 = ldpair(&mg[c * 130 + 2 * lane]);
        ull m1 = ldpair(&mg[c * 130 + 2 * lane + 64]);
#pragma unroll
        for (int j = 0; j < 16; j++) {
            ull wv = splat2(Wzs[(wp + 16 * j) * 32 + c]);
            acc[j][0] = fma2(wv, m0, acc[j][0]);
            acc[j][1] = fma2(wv, m1, acc[j][1]);
        }
    }

#pragma unroll
    for (int j = 0; j < 16; j++) {
        int o = wp + 16 * j;
        float bias = bz[o];
        size_t obase = ((size_t)(b * C_ + o) * H_ + h) * W_;
#pragma unroll
        for (int u = 0; u < 2; u++) {
            int w = 2 * lane + 64 * u;
            float2 xv = *reinterpret_cast<const float2*>(&x[obase + w]);
            float2 a  = unpack2(acc[j][u]);
            a.x += bias + xv.x;
            a.y += bias + xv.y;
            *reinterpret_cast<float2*>(&out[obase + w]) = a;
        }
    }
}

// ---------------- launch ------------------------------------------------------
extern "C" void kernel_launch(void* const* d_in, const int* in_sizes, int n_in,
                              void* d_out, int out_size)
{
    const float* x  = (const float*)d_in[0];
    const float* Wq = (const float*)d_in[1];
    const float* bq = (const float*)d_in[2];
    const float* Wk = (const float*)d_in[3];
    const float* bk = (const float*)d_in[4];
    const float* Wv = (const float*)d_in[5];
    const float* bv = (const float*)d_in[6];
    const float* Wz = (const float*)d_in[7];
    const float* bz = (const float*)d_in[8];
    float* out = (float*)d_out;

    cudaFuncSetAttribute(attn_kernel,    cudaFuncAttributeMaxDynamicSharedMemorySize, ATTN_SMEM);
    cudaFuncSetAttribute(combine_kernel, cudaFuncAttributeMaxDynamicSharedMemorySize, COMB_SMEM);

    proj_kernel<<<dim3(H_, B_), 256>>>(x, Wq, bq, Wk, bk, Wv, bv);
    transpose_kernel<<<dim3(4, 4, 3 * 256), dim3(32, 8)>>>(0);   // q,k,v -> qt,kt,vt
    attn_kernel<<<dim3(W_, B_), 256, ATTN_SMEM>>>(1);            // H path
    attn_kernel<<<dim3(H_, B_), 256, ATTN_SMEM>>>(0);            // W path
    transpose_kernel<<<dim3(4, 4, 256), dim3(32, 8)>>>(3);       // oH -> oHt
    combine_kernel<<<dim3(H_, B_), 512, COMB_SMEM>>>(x, Wz, bz, out);
}

// round 8
// speedup vs baseline: 1.1235x; 1.0033x over previous
#include <cuda_runtime.h>

typedef unsigned long long ull;
typedef unsigned int uint_;

#define B_   8
#define C_   256
#define H_   128
#define W_   128
#define CR_  32
#define HW_  (H_ * W_)

// ---------------- scratch (device globals; no runtime allocation) -------------
__device__ float g_q  [B_ * CR_ * HW_];   // (b, cr, h, w)
__device__ float g_k  [B_ * CR_ * HW_];
__device__ float g_v  [B_ * CR_ * HW_];
__device__ float g_qt [B_ * CR_ * HW_];   // (b, cr, w, h)
__device__ float g_kt [B_ * CR_ * HW_];
__device__ float g_vt [B_ * CR_ * HW_];
__device__ float g_oH [B_ * CR_ * HW_];   // (b, cr, w, h)
__device__ float g_oHt[B_ * CR_ * HW_];   // (b, cr, h, w)
__device__ float g_oW [B_ * CR_ * HW_];   // (b, cr, h, w)
__device__ float g_mH [B_ * HW_];
__device__ float g_sH [B_ * HW_];
__device__ float g_mW [B_ * HW_];
__device__ float g_sW [B_ * HW_];

// ---------------- packed f32x2 helpers ---------------------------------------
__device__ __forceinline__ ull fma2(ull a, ull b, ull c) {
    ull d;
    asm("fma.rn.f32x2 %0, %1, %2, %3;" : "=l"(d) : "l"(a), "l"(b), "l"(c));
    return d;
}
__device__ __forceinline__ ull splat2(float f) {
    ull r; uint_ u = __float_as_uint(f);
    asm("mov.b64 %0, {%1, %1};" : "=l"(r) : "r"(u));
    return r;
}
__device__ __forceinline__ ull pack2(float lo, float hi) {
    ull r;
    asm("mov.b64 %0, {%1, %2};" : "=l"(r)
        : "r"(__float_as_uint(lo)), "r"(__float_as_uint(hi)));
    return r;
}
__device__ __forceinline__ float2 unpack2(ull u) {
    uint_ lo, hi;
    asm("mov.b64 {%0, %1}, %2;" : "=r"(lo), "=r"(hi) : "l"(u));
    return make_float2(__uint_as_float(lo), __uint_as_float(hi));
}
__device__ __forceinline__ ull ldpair(const float* p) {
    union { float2 f2; ull u; } t;
    t.f2 = *reinterpret_cast<const float2*>(p);
    return t.u;
}

union F4U { float4 f4; ull u[2]; };

// bf16 hi/lo split: hi2/lo2 pack (elem0 -> low half, elem1 -> high half)
__device__ __forceinline__ void split_bf16(float x0, float x1, uint_& hi2, uint_& lo2) {
    asm("cvt.rn.satfinite.bf16x2.f32 %0, %1, %2;" : "=r"(hi2) : "f"(x1), "f"(x0));
    float h0 = __uint_as_float(hi2 << 16);
    float h1 = __uint_as_float(hi2 & 0xffff0000u);
    float l0 = x0 - h0, l1 = x1 - h1;
    asm("cvt.rn.satfinite.bf16x2.f32 %0, %1, %2;" : "=r"(lo2) : "f"(l1), "f"(l0));
}

// warp-level bf16 MMA: D(16x8,f32) += A(16x16,bf16 row) * B(16x8,bf16 col)
__device__ __forceinline__ void mma_bf16(float* d, const uint_* a, const uint_* b) {
    asm volatile(
        "mma.sync.aligned.m16n8k16.row.col.f32.bf16.bf16.f32 "
        "{%0,%1,%2,%3}, {%4,%5,%6,%7}, {%8,%9}, {%0,%1,%2,%3};"
        : "+f"(d[0]), "+f"(d[1]), "+f"(d[2]), "+f"(d[3])
        : "r"(a[0]), "r"(a[1]), "r"(a[2]), "r"(a[3]), "r"(b[0]), "r"(b[1]));
}

// ---------------- kernel 1: q/k/v projection via mma.sync bf16-split ----------
// grid (H, B), 256 threads. D[96 out][128 pix] = W(96x256) . x(256x128)
// smem layout (uint32 units):
//   Wph[96][36], Wpl[96][36], Xph[32][136], Xpl[32][136], bias[96]
#define PJ_WPH   0
#define PJ_WPL   (96 * 36)
#define PJ_XPH   (2 * 96 * 36)
#define PJ_XPL   (2 * 96 * 36 + 32 * 136)
#define PJ_BIAS  (2 * 96 * 36 + 2 * 32 * 136)
#define PROJ_SMEM ((2 * 96 * 36 + 2 * 32 * 136 + 96) * 4)

__global__ void __launch_bounds__(256, 2) proj_mma_kernel(
    const float* __restrict__ x,
    const float* __restrict__ Wq, const float* __restrict__ bq,
    const float* __restrict__ Wk, const float* __restrict__ bk,
    const float* __restrict__ Wv, const float* __restrict__ bv)
{
    extern __shared__ uint_ ps[];
    uint_* Wph = ps + PJ_WPH;
    uint_* Wpl = ps + PJ_WPL;
    uint_* Xph = ps + PJ_XPH;
    uint_* Xpl = ps + PJ_XPL;
    float* bsm = reinterpret_cast<float*>(ps + PJ_BIAS);

    int h = blockIdx.x, b = blockIdx.y;
    int tid = threadIdx.x;
    int wid = tid >> 5, lane = tid & 31;
    int g = lane >> 2, tg = lane & 3;
    int wm = wid >> 2, wn = wid & 3;           // 2 x 4 warp grid
    int m0 = wm * 48, n0 = wn * 32;

    if (tid < 96) {
        float bv_;
        if (tid < 32)      bv_ = bq[tid];
        else if (tid < 64) bv_ = bk[tid - 32];
        else               bv_ = bv[tid - 64];
        bsm[tid] = bv_;
    }

    const float* xb = x + (size_t)b * C_ * HW_ + (size_t)h * W_;

    float acc[3][4][4];
#pragma unroll
    for (int mt = 0; mt < 3; mt++)
#pragma unroll
        for (int nt = 0; nt < 4; nt++)
#pragma unroll
            for (int u = 0; u < 4; u++) acc[mt][nt][u] = 0.f;

    int pixld = tid & 127, halfld = tid >> 7;

    for (int kc = 0; kc < 4; kc++) {
        if (kc) __syncthreads();
        // ---- weights chunk: 96 rows x 32 kpairs ----
        for (int idx = tid; idx < 96 * 32; idx += 256) {
            int r = idx >> 5, kp = idx & 31;
            const float* wsrc;
            if (r < 32)      wsrc = Wq + (size_t)r * C_;
            else if (r < 64) wsrc = Wk + (size_t)(r - 32) * C_;
            else             wsrc = Wv + (size_t)(r - 64) * C_;
            float w0 = wsrc[kc * 64 + 2 * kp];
            float w1 = wsrc[kc * 64 + 2 * kp + 1];
            uint_ hi2, lo2;
            split_bf16(w0, w1, hi2, lo2);
            Wph[r * 36 + kp] = hi2;
            Wpl[r * 36 + kp] = lo2;
        }
        // ---- x chunk: 32 kpairs x 128 pix ----
#pragma unroll 4
        for (int kp2 = 0; kp2 < 16; kp2++) {
            int kp = kp2 * 2 + halfld;
            int c = kc * 64 + 2 * kp;
            float x0 = xb[(size_t)c * HW_ + pixld];
            float x1 = xb[(size_t)(c + 1) * HW_ + pixld];
            uint_ hi2, lo2;
            split_bf16(x0, x1, hi2, lo2);
            Xph[kp * 136 + pixld] = hi2;
            Xpl[kp * 136 + pixld] = lo2;
        }
        __syncthreads();

        // ---- 4 k16-steps over this chunk ----
#pragma unroll
        for (int ks = 0; ks < 4; ks++) {
            int kpb = ks * 8;
            uint_ bh[4][2], bl[4][2];
#pragma unroll
            for (int nt = 0; nt < 4; nt++) {
                int n = n0 + nt * 8 + g;
                bh[nt][0] = Xph[(kpb + tg) * 136 + n];
                bh[nt][1] = Xph[(kpb + tg + 4) * 136 + n];
                bl[nt][0] = Xpl[(kpb + tg) * 136 + n];
                bl[nt][1] = Xpl[(kpb + tg + 4) * 136 + n];
            }
#pragma unroll
            for (int mt = 0; mt < 3; mt++) {
                int m = m0 + mt * 16 + g;
                uint_ ah[4], al[4];
                ah[0] = Wph[m * 36 + kpb + tg];
                ah[1] = Wph[(m + 8) * 36 + kpb + tg];
                ah[2] = Wph[m * 36 + kpb + tg + 4];
                ah[3] = Wph[(m + 8) * 36 + kpb + tg + 4];
                al[0] = Wpl[m * 36 + kpb + tg];
                al[1] = Wpl[(m + 8) * 36 + kpb + tg];
                al[2] = Wpl[m * 36 + kpb + tg + 4];
                al[3] = Wpl[(m + 8) * 36 + kpb + tg + 4];
#pragma unroll
                for (int nt = 0; nt < 4; nt++) {
                    mma_bf16(acc[mt][nt], ah, bh[nt]);
                    mma_bf16(acc[mt][nt], ah, bl[nt]);
                    mma_bf16(acc[mt][nt], al, bh[nt]);
                }
            }
        }
    }

    // ---- epilogue: bias + store to g_q/g_k/g_v ----
#pragma unroll
    for (int mt = 0; mt < 3; mt++) {
#pragma unroll
        for (int half = 0; half < 2; half++) {
            int r = m0 + mt * 16 + g + 8 * half;
            float bias = bsm[r];
            float* dstb;
            int ch;
            if (r < 32)      { dstb = g_q; ch = r; }
            else if (r < 64) { dstb = g_k; ch = r - 32; }
            else             { dstb = g_v; ch = r - 64; }
            float* drow = dstb + ((size_t)(b * CR_ + ch) * H_ + h) * W_;
#pragma unroll
            for (int nt = 0; nt < 4; nt++) {
                int pix = n0 + nt * 8 + 2 * tg;
                float2 v;
                v.x = acc[mt][nt][2 * half]     + bias;
                v.y = acc[mt][nt][2 * half + 1] + bias;
                *reinterpret_cast<float2*>(&drow[pix]) = v;
            }
        }
    }
}

// ---------------- kernel 2: HxW tile transpose --------------------------------
__global__ void __launch_bounds__(256) transpose_kernel(int base_arr)
{
    __shared__ float tile[32][33];
    int zc = blockIdx.z;
    int arr = base_arr + (zc >> 8), m = zc & 255;
    const float* src; float* dst;
    if      (arr == 0) { src = g_q;  dst = g_qt;  }
    else if (arr == 1) { src = g_k;  dst = g_kt;  }
    else if (arr == 2) { src = g_v;  dst = g_vt;  }
    else               { src = g_oH; dst = g_oHt; }
    src += (size_t)m * HW_;
    dst += (size_t)m * HW_;
    int x0 = blockIdx.x * 32, y0 = blockIdx.y * 32;
    int tx = threadIdx.x, ty = threadIdx.y;
#pragma unroll
    for (int r = 0; r < 32; r += 8)
        tile[ty + r][tx] = src[(size_t)(y0 + ty + r) * W_ + x0 + tx];
    __syncthreads();
#pragma unroll
    for (int r = 0; r < 32; r += 8)
        dst[(size_t)(x0 + ty + r) * H_ + y0 + tx] = tile[tx][ty + r];
}

// ---------------- kernel 3: attention path (round-5 version) -----------------
#define ATTN_SMEM ((32 * 132 + 32 * 128 + 128 * 33 + 128 * 128) * 4)

__global__ void __launch_bounds__(256) attn_kernel(int transposed)
{
    extern __shared__ float sm[];
    float* Qs  = sm;                        // 32 x 132
    float* Ks  = sm + 32 * 132;             // 32 x 128
    float* Vst = Ks + 32 * 128;             // 128 x 33
    float* E   = Vst + 128 * 33;            // 128 x 128

    const float* qin = transposed ? g_qt : g_q;
    const float* kin = transposed ? g_kt : g_k;
    const float* vin = transposed ? g_vt : g_v;
    float* outp  = transposed ? g_oH : g_oW;
    float* mstat = transposed ? g_mH : g_mW;
    float* sstat = transposed ? g_sH : g_sW;

    int X = blockIdx.x, b = blockIdx.y;
    size_t base = (size_t)b * CR_ * HW_ + (size_t)X * W_;
    int tid = threadIdx.x, warp = tid >> 5, lane = tid & 31;

    for (int idx = tid; idx < CR_ * 128; idx += 256) {
        int c = idx >> 7, e = idx & 127;
        Qs[c * 132 + e] = qin[base + (size_t)c * HW_ + e];
        Ks[c * 128 + e] = kin[base + (size_t)c * HW_ + e];
        Vst[e * 33 + c] = vin[base + (size_t)c * HW_ + e];
    }
    __syncthreads();

    ull acc[16][2];
#pragma unroll
    for (int t = 0; t < 16; t++) { acc[t][0] = 0ull; acc[t][1] = 0ull; }

#pragma unroll 2
    for (int c = 0; c < 32; c++) {
        ull k0 = ldpair(&Ks[c * 128 + 2 * lane]);
        ull k1 = ldpair(&Ks[c * 128 + 2 * lane + 64]);
        float4 q0 = *reinterpret_cast<const float4*>(&Qs[c * 132 + 16 * warp]);
        float4 q1 = *reinterpret_cast<const float4*>(&Qs[c * 132 + 16 * warp + 4]);
        float4 q2 = *reinterpret_cast<const float4*>(&Qs[c * 132 + 16 * warp + 8]);
        float4 q3 = *reinterpret_cast<const float4*>(&Qs[c * 132 + 16 * warp + 12]);
#define GSTEP(T, QF) { ull qv = splat2(QF); \
        acc[T][0] = fma2(qv, k0, acc[T][0]); acc[T][1] = fma2(qv, k1, acc[T][1]); }
        GSTEP(0,  q0.x) GSTEP(1,  q0.y) GSTEP(2,  q0.z) GSTEP(3,  q0.w)
        GSTEP(4,  q1.x) GSTEP(5,  q1.y) GSTEP(6,  q1.z) GSTEP(7,  q1.w)
        GSTEP(8,  q2.x) GSTEP(9,  q2.y) GSTEP(10, q2.z) GSTEP(11, q2.w)
        GSTEP(12, q3.x) GSTEP(13, q3.y) GSTEP(14, q3.z) GSTEP(15, q3.w)
#undef GSTEP
    }

#pragma unroll
    for (int t = 0; t < 16; t++) {
        int r = warp * 16 + t;
        float2 a0 = unpack2(acc[t][0]);
        float2 a1 = unpack2(acc[t][1]);
        if (transposed) {
            int i0 = 2 * lane;
            if (i0      == r) a0.x = -1e30f;
            if (i0 + 1  == r) a0.y = -1e30f;
            if (i0 + 64 == r) a1.x = -1e30f;
            if (i0 + 65 == r) a1.y = -1e30f;
        }
        float mx = fmaxf(fmaxf(a0.x, a0.y), fmaxf(a1.x, a1.y));
#pragma unroll
        for (int o = 16; o > 0; o >>= 1) mx = fmaxf(mx, __shfl_xor_sync(0xffffffffu, mx, o));
        float p0 = __expf(a0.x - mx), p1 = __expf(a0.y - mx);
        float p2 = __expf(a1.x - mx), p3 = __expf(a1.y - mx);
        float sum = (p0 + p1) + (p2 + p3);
#pragma unroll
        for (int o = 16; o > 0; o >>= 1) sum += __shfl_xor_sync(0xffffffffu, sum, o);
        *reinterpret_cast<float2*>(&E[r * 128 + 2 * lane])      = make_float2(p0, p1);
        *reinterpret_cast<float2*>(&E[r * 128 + 2 * lane + 64]) = make_float2(p2, p3);
        if (lane == 0) {
            size_t sidx = transposed ? ((size_t)(b * H_ + r) * W_ + X)
                                     : ((size_t)(b * H_ + X) * W_ + r);
            mstat[sidx] = mx;
            sstat[sidx] = sum;
        }
    }
    __syncthreads();

    ull agg[16];
#pragma unroll
    for (int t = 0; t < 16; t++) agg[t] = 0ull;

    for (int i = 0; i < 128; i += 8) {
        ull vv[4];
#pragma unroll
        for (int u = 0; u < 4; u++)
            vv[u] = pack2(Vst[(i + 2 * u) * 33 + lane], Vst[(i + 2 * u + 1) * 33 + lane]);
#pragma unroll
        for (int t = 0; t < 16; t++) {
            F4U e0, e1;
            e0.f4 = *reinterpret_cast<const float4*>(&E[(warp * 16 + t) * 128 + i]);
            e1.f4 = *reinterpret_cast<const float4*>(&E[(warp * 16 + t) * 128 + i + 4]);
            agg[t] = fma2(e0.u[0], vv[0], agg[t]);
            agg[t] = fma2(e0.u[1], vv[1], agg[t]);
            agg[t] = fma2(e1.u[0], vv[2], agg[t]);
            agg[t] = fma2(e1.u[1], vv[3], agg[t]);
        }
    }

#pragma unroll
    for (int t = 0; t < 16; t++) {
        float2 s = unpack2(agg[t]);
        Qs[lane * 130 + warp * 16 + t] = s.x + s.y;
    }
    __syncthreads();
    for (int idx = tid; idx < CR_ * 128; idx += 256) {
        int c = idx >> 7, e = idx & 127;
        outp[base + (size_t)c * HW_ + e] = Qs[c * 130 + e];
    }
}

// ---------------- kernel 4: softmax merge + Wz conv + bias + residual --------
#define COMB_SMEM ((32 * 130 + 256 * 32 + 256) * 4)

__global__ void __launch_bounds__(512) combine_kernel(
    const float* __restrict__ x, const float* __restrict__ Wz,
    const float* __restrict__ bz, float* __restrict__ out)
{
    extern __shared__ float sm[];
    float* mg  = sm;                        // 32 x 130
    float* Wzs = sm + 32 * 130;             // 256 x 32
    float* fH  = sm + 32 * 130 + 256 * 32;  // 128
    float* fW  = fH + 128;                  // 128

    int h = blockIdx.x, b = blockIdx.y;
    int tid = threadIdx.x, wp = tid >> 5, lane = tid & 31;

    if (tid < 128) {
        int w = tid;
        size_t sidx = (size_t)(b * H_ + h) * W_ + w;
        float mh = g_mH[sidx], mw = g_mW[sidx];
        float sh = g_sH[sidx], sw = g_sW[sidx];
        float m  = fmaxf(mh, mw);
        float eh = __expf(mh - m), ew = __expf(mw - m);
        float inv = 1.0f / (sh * eh + sw * ew);
        fH[w] = eh * inv;
        fW[w] = ew * inv;
    }
    for (int idx = tid; idx < 256 * 32; idx += 512)
        Wzs[idx] = Wz[idx];
    __syncthreads();

    for (int idx = tid; idx < 32 * 128; idx += 512) {
        int c = idx >> 7, w = idx & 127;
        size_t off = (size_t)(b * CR_ + c) * HW_ + (size_t)h * W_ + w;
        mg[c * 130 + w] = g_oHt[off] * fH[w] + g_oW[off] * fW[w];
    }
    __syncthreads();

    ull acc[16][2];
#pragma unroll
    for (int j = 0; j < 16; j++) { acc[j][0] = 0ull; acc[j][1] = 0ull; }

#pragma unroll 4
    for (int c = 0; c < 32; c++) {
        ull m0 = ldpair(&mg[c * 130 + 2 * lane]);
        ull m1 = ldpair(&mg[c * 130 + 2 * lane + 64]);
#pragma unroll
        for (int j = 0; j < 16; j++) {
            ull wv = splat2(Wzs[(wp + 16 * j) * 32 + c]);
            acc[j][0] = fma2(wv, m0, acc[j][0]);
            acc[j][1] = fma2(wv, m1, acc[j][1]);
        }
    }

#pragma unroll
    for (int j = 0; j < 16; j++) {
        int o = wp + 16 * j;
        float bias = bz[o];
        size_t obase = ((size_t)(b * C_ + o) * H_ + h) * W_;
#pragma unroll
        for (int u = 0; u < 2; u++) {
            int w = 2 * lane + 64 * u;
            float2 xv = *reinterpret_cast<const float2*>(&x[obase + w]);
            float2 a  = unpack2(acc[j][u]);
            a.x += bias + xv.x;
            a.y += bias + xv.y;
            *reinterpret_cast<float2*>(&out[obase + w]) = a;
        }
    }
}

// ---------------- launch ------------------------------------------------------
extern "C" void kernel_launch(void* const* d_in, const int* in_sizes, int n_in,
                              void* d_out, int out_size)
{
    const float* x  = (const float*)d_in[0];
    const float* Wq = (const float*)d_in[1];
    const float* bq = (const float*)d_in[2];
    const float* Wk = (const float*)d_in[3];
    const float* bk = (const float*)d_in[4];
    const float* Wv = (const float*)d_in[5];
    const float* bv = (const float*)d_in[6];
    const float* Wz = (const float*)d_in[7];
    const float* bz = (const float*)d_in[8];
    float* out = (float*)d_out;

    cudaFuncSetAttribute(proj_mma_kernel, cudaFuncAttributeMaxDynamicSharedMemorySize, PROJ_SMEM);
    cudaFuncSetAttribute(attn_kernel,     cudaFuncAttributeMaxDynamicSharedMemorySize, ATTN_SMEM);
    cudaFuncSetAttribute(combine_kernel,  cudaFuncAttributeMaxDynamicSharedMemorySize, COMB_SMEM);

    proj_mma_kernel<<<dim3(H_, B_), 256, PROJ_SMEM>>>(x, Wq, bq, Wk, bk, Wv, bv);
    transpose_kernel<<<dim3(4, 4, 3 * 256), dim3(32, 8)>>>(0);   // q,k,v -> qt,kt,vt
    attn_kernel<<<dim3(W_, B_), 256, ATTN_SMEM>>>(1);            // H path
    attn_kernel<<<dim3(H_, B_), 256, ATTN_SMEM>>>(0);            // W path
    transpose_kernel<<<dim3(4, 4, 256), dim3(32, 8)>>>(3);       // oH -> oHt
    combine_kernel<<<dim3(H_, B_), 512, COMB_SMEM>>>(x, Wz, bz, out);
}